// round 11
// baseline (speedup 1.0000x reference)
#include <cuda_runtime.h>
#include <cstdint>

// ---------------------------------------------------------------------------
// SetAbstraction (PointNet++): FPS -> ball query -> MLP -> max
// B=2, N=16384, S=4096, K=32, F_IN=16, hidden 64-64-128
// Round 11 FPS: R10 (XOR cell remap, packed REDUX, single barrier) +
//   - register z-carry reinstated (removes the serial L2 LDG gz[wp] from
//     every iteration's critical path; z rides shuffles/parity buffers)
//   - per-lane self-prefetch of own touched cell BEFORE the ballot
// Selection sequence bit-identical to the naive scan.
// ---------------------------------------------------------------------------

#define BB   2
#define NN   16384
#define SS   4096
#define KK   32
#define FIN  16
#define HOUT 128
#define GC    8
#define NCELL 512
#define CW    0.125f
#define FULLM 0xffffffffu

// ---- scratch (__device__ globals; no allocation allowed) -------------------
__device__ float g_centers[BB * SS * 3];
__device__ int   g_nbr[BB * SS * KK];
__device__ int   g_cnt[BB * SS];

__device__ float2 g_sxy[BB * NN];      // sorted (x,y)
__device__ int2   g_szi[BB * NN];      // sorted (z bits, orig idx)
__device__ int    g_hist[BB * NCELL];
__device__ int    g_cstart[BB * (NCELL + 1)];
__device__ int    g_fill[BB * NCELL];

__device__ __forceinline__ int cell_of(float x, float y, float z) {
    int ix = (int)(x * (float)GC); ix = ix < 0 ? 0 : (ix > GC - 1 ? GC - 1 : ix);
    int iy = (int)(y * (float)GC); iy = iy < 0 ? 0 : (iy > GC - 1 ? GC - 1 : iy);
    int iz = (int)(z * (float)GC); iz = iz < 0 ? 0 : (iz > GC - 1 ? GC - 1 : iz);
    return (iz * GC + iy) * GC + ix;
}

// ===========================================================================
// Preprocessing: histogram -> scan -> scatter (counting sort by cell)
// ===========================================================================
__global__ void init_hist_kernel() {
    int i = blockIdx.x * blockDim.x + threadIdx.x;
    if (i < BB * NCELL) g_hist[i] = 0;
}

__global__ void cell_count_kernel(const float* __restrict__ pos) {
    int i = blockIdx.x * blockDim.x + threadIdx.x;
    if (i >= BB * NN) return;
    int b = i >> 14;
    float x = pos[(size_t)i * 3 + 0], y = pos[(size_t)i * 3 + 1], z = pos[(size_t)i * 3 + 2];
    atomicAdd(&g_hist[b * NCELL + cell_of(x, y, z)], 1);
}

__global__ void cell_scan_kernel() {
    __shared__ int sh[NCELL];
    __shared__ int ss[NCELL + 1];
    int b = blockIdx.x, tid = threadIdx.x;
    if (tid < NCELL) sh[tid] = g_hist[b * NCELL + tid];
    __syncthreads();
    if (tid == 0) {
        int acc = 0;
        for (int c = 0; c < NCELL; c++) { ss[c] = acc; acc += sh[c]; }
        ss[NCELL] = acc;
    }
    __syncthreads();
    if (tid < NCELL) {
        g_cstart[b * (NCELL + 1) + tid] = ss[tid];
        g_fill[b * NCELL + tid] = ss[tid];
    }
    if (tid == 0) g_cstart[b * (NCELL + 1) + NCELL] = ss[NCELL];
}

__global__ void cell_scatter_kernel(const float* __restrict__ pos) {
    int i = blockIdx.x * blockDim.x + threadIdx.x;
    if (i >= BB * NN) return;
    int b = i >> 14;
    int li = i & (NN - 1);
    float x = pos[(size_t)i * 3 + 0], y = pos[(size_t)i * 3 + 1], z = pos[(size_t)i * 3 + 2];
    int c = cell_of(x, y, z);
    int p = atomicAdd(&g_fill[b * NCELL + c], 1);
    g_sxy[b * NN + p] = make_float2(x, y);
    g_szi[b * NN + p] = make_int2(__float_as_int(z), li);
}

// ===========================================================================
// Kernel 1: grid-pruned exact FPS. One block per batch, 512 threads (16 warps).
// Cell assignment: p = w + 16*lane, cell = p ^ ((p>>6)*9)  (XOR bijection).
// Per-lane scan key u64 = (dmin_bits<<28)|(~origidx&0x3fff)<<14|sorted_pos.
// ONE __syncthreads per iteration (double-buffered partials). z carried in
// registers/shuffles -- no serial global load on the iteration chain.
// ===========================================================================
__global__ void __launch_bounds__(512, 1)
fps_kernel(const float* __restrict__ pos, float* __restrict__ out_centers)
{
    extern __shared__ float sm[];
    float2* s_xy   = (float2*)sm;        // NN float2 (128 KB)
    float*  s_dmin = sm + 2 * NN;        // NN floats (64 KB)

    __shared__ unsigned long long s_part[2][16];  // parity-buffered partials
    __shared__ float              s_pz[2][16];    // parity-buffered winner z

    const int b = blockIdx.x, tid = threadIdx.x;
    const int w = tid >> 5, lane = tid & 31;
    const int base = b * NN;
    const int2* __restrict__ gz = g_szi + base;

    for (int p = tid; p < NN; p += 512) {
        s_xy[p] = g_sxy[base + p];
        s_dmin[p] = 1e10f;
    }
    if (tid < 16) {
        s_part[0][tid] = 0ULL; s_part[1][tid] = 0ULL;
        s_pz[0][tid] = 0.f;    s_pz[1][tid] = 0.f;
    }

    // this lane's owned cell (XOR bijection spreads x, y AND z neighbors)
    const int pidx = w + (lane << 4);
    const int cell = pidx ^ ((pidx >> 6) * 9);
    const int cs0 = g_cstart[b * (NCELL + 1) + cell];
    const int cs1 = g_cstart[b * (NCELL + 1) + cell + 1];
    const int ix = cell & 7, iy = (cell >> 3) & 7, iz = cell >> 6;
    const float lox = (float)ix * CW - 1e-5f, hix = (float)ix * CW + CW + 1e-5f;
    const float loy = (float)iy * CW - 1e-5f, hiy = (float)iy * CW + CW + 1e-5f;
    const float loz = (float)iz * CW - 1e-5f, hiz = (float)iz * CW + CW + 1e-5f;

    unsigned kv    = __float_as_uint(1e10f);   // cached cell key: max dmin bits
    unsigned kcand = 0u;                       // (lo14<<14)|p of winner
    float    kz    = 0.f;                      // winner z (register carry)

    // initial center (deterministic start at original point 0), in registers
    float cx = pos[(size_t)base * 3 + 0];
    float cy = pos[(size_t)base * 3 + 1];
    float cz = pos[(size_t)base * 3 + 2];
    if (tid == 0) {
        int row = b * SS;
        out_centers[row * 3 + 0] = cx; out_centers[row * 3 + 1] = cy; out_centers[row * 3 + 2] = cz;
        g_centers[row * 3 + 0]   = cx; g_centers[row * 3 + 1]   = cy; g_centers[row * 3 + 2]   = cz;
    }
    __syncthreads();

    for (int t = 1; t < SS; t++) {
        const int par = t & 1;

        // --- prune: each lane checks its own cell --------------------------
        float pdx = fmaxf(fmaxf(lox - cx, cx - hix), 0.f);
        float pdy = fmaxf(fmaxf(loy - cy, cy - hiy), 0.f);
        float pdz = fmaxf(fmaxf(loz - cz, cz - hiz), 0.f);
        float lb  = (pdx * pdx + pdy * pdy + pdz * pdz) * 0.999f;
        bool touched = lb < __uint_as_float(kv);

        // self-prefetch own cell's first lines BEFORE the ballot (no reg dep)
        if (touched) {
            const int2* pf0 = &gz[cs0];
            asm volatile("prefetch.global.L1 [%0];" :: "l"(pf0));
            if (cs0 + 16 < cs1) {
                const int2* pf1 = &gz[cs0 + 16];
                asm volatile("prefetch.global.L1 [%0];" :: "l"(pf1));
            }
        }
        unsigned tmask = __ballot_sync(FULLM, touched);

        if (tmask) {
            // --- process touched cells (pipelined next-cell preload) -------
            int j = __ffs(tmask) - 1; tmask &= tmask - 1;
            int st = __shfl_sync(FULLM, cs0, j);
            int en = __shfl_sync(FULLM, cs1, j);
            int p0v = st + lane; bool v = p0v < en;
            int2 zi = make_int2(0, 0); float2 xy = make_float2(0.f, 0.f);
            if (v) { zi = gz[p0v]; xy = s_xy[p0v]; }
            while (j >= 0) {
                unsigned long long best = 0ULL; float bz = 0.f;
                if (v) {
                    int p = st + lane;
                    float zz  = __int_as_float(zi.x);
                    float ddx = __fsub_rn(xy.x, cx);
                    float ddy = __fsub_rn(xy.y, cy);
                    float ddz = __fsub_rn(zz,   cz);
                    float d   = __fadd_rn(__fadd_rn(__fmul_rn(ddx, ddx), __fmul_rn(ddy, ddy)),
                                          __fmul_rn(ddz, ddz));
                    float dm  = fminf(s_dmin[p], d);
                    s_dmin[p] = dm;
                    unsigned lo14 = (~(unsigned)zi.y) & 0x3fffu;
                    best = (((unsigned long long)__float_as_uint(dm)) << 28)
                         | ((unsigned long long)lo14 << 14)
                         | (unsigned long long)p;
                    bz = zz;
                }
                // preload next touched cell's first chunk
                int jn = -1, stn = 0, enn = 0; bool vn = false;
                int2 zin = make_int2(0, 0); float2 xyn = make_float2(0.f, 0.f);
                if (tmask) {
                    jn = __ffs(tmask) - 1; tmask &= tmask - 1;
                    stn = __shfl_sync(FULLM, cs0, jn);
                    enn = __shfl_sync(FULLM, cs1, jn);
                    int p = stn + lane; vn = p < enn;
                    if (vn) { zin = gz[p]; xyn = s_xy[p]; }
                }
                // remaining chunks of current cell
                for (int pp = st + 32; pp < en; pp += 32) {
                    int p = pp + lane;
                    if (p < en) {
                        int2   z2 = gz[p];
                        float2 x2 = s_xy[p];
                        float zz  = __int_as_float(z2.x);
                        float ddx = __fsub_rn(x2.x, cx);
                        float ddy = __fsub_rn(x2.y, cy);
                        float ddz = __fsub_rn(zz,   cz);
                        float d   = __fadd_rn(__fadd_rn(__fmul_rn(ddx, ddx), __fmul_rn(ddy, ddy)),
                                              __fmul_rn(ddz, ddz));
                        float dm  = fminf(s_dmin[p], d);
                        s_dmin[p] = dm;
                        unsigned lo14 = (~(unsigned)z2.y) & 0x3fffu;
                        unsigned long long pk =
                            (((unsigned long long)__float_as_uint(dm)) << 28)
                            | ((unsigned long long)lo14 << 14)
                            | (unsigned long long)p;
                        if (pk > best) { best = pk; bz = zz; }
                    }
                }
                // cell key via packed REDUX (identity rides in the value)
                unsigned du    = (unsigned)(best >> 28);
                unsigned wm    = __reduce_max_sync(FULLM, du);
                unsigned cand  = (du == wm) ? (unsigned)(best & 0xFFFFFFFull) : 0u;
                unsigned mcand = __reduce_max_sync(FULLM, cand);
                int wp  = (int)(mcand & 0x3fffu);
                int src = (wp - st) & 31;
                float zw = __shfl_sync(FULLM, bz, src);
                if (lane == j) { kv = wm; kcand = mcand; kz = zw; }
                j = jn; st = stn; en = enn; v = vn; zi = zin; xy = xyn;
            }

            // per-warp partial over its 32 owned cells -> parity buffer
            unsigned mv  = __reduce_max_sync(FULLM, kv);
            unsigned c2  = (kv == mv) ? kcand : 0u;
            unsigned mc2 = __reduce_max_sync(FULLM, c2);
            if (kv == mv && kcand == mc2) {   // unique (mc2 embeds unique p)
                s_part[par][w] = (((unsigned long long)mv) << 32) | mc2;
                s_pz[par][w]   = kz;
            }
        } else {
            // untouched warp: partial unchanged; copy across parity
            if (lane == 0) {
                s_part[par][w] = s_part[par ^ 1][w];
                s_pz[par][w]   = s_pz[par ^ 1][w];
            }
        }
        __syncthreads();   // the ONLY barrier per iteration

        // --- redundant final argmax over 16 partials (every warp) ----------
        unsigned long long pk = (lane < 16) ? s_part[par][lane] : 0ULL;
        float pz = (lane < 16) ? s_pz[par][lane] : 0.f;
        unsigned hi = (unsigned)(pk >> 32), lo = (unsigned)pk;
        unsigned mv2 = __reduce_max_sync(FULLM, hi);
        unsigned c3  = (hi == mv2) ? lo : 0u;
        unsigned mc3 = __reduce_max_sync(FULLM, c3);
        unsigned bm  = __ballot_sync(FULLM, (hi == mv2) && (lo == mc3));
        int src = __ffs(bm) - 1;
        int wp  = (int)(mc3 & 0x3fffu);
        float zw = __shfl_sync(FULLM, pz, src);
        float2 xyw = s_xy[wp];                       // broadcast LDS (29 cy)
        cx = xyw.x; cy = xyw.y; cz = zw;             // next center, in regs
        if (w == 0 && lane == src) {
            int row = b * SS + t;
            out_centers[row * 3 + 0] = cx; out_centers[row * 3 + 1] = cy; out_centers[row * 3 + 2] = cz;
            g_centers[row * 3 + 0]   = cx; g_centers[row * 3 + 1]   = cy; g_centers[row * 3 + 2]   = cz;
        }
    }
}

// ===========================================================================
// Kernel 2: Ball query — one warp per center; ordered scan, first K within R.
// ===========================================================================
__global__ void __launch_bounds__(256, 8)
ballq_kernel(const float* __restrict__ pos, float* __restrict__ out_batch)
{
    const int w    = (blockIdx.x * blockDim.x + threadIdx.x) >> 5;
    const int lane = threadIdx.x & 31;
    if (w >= BB * SS) return;

    const int b = w >> 12;
    const int s = w & (SS - 1);
    const float* pb = pos + (size_t)b * NN * 3;

    const float cx = g_centers[w * 3 + 0];
    const float cy = g_centers[w * 3 + 1];
    const float cz = g_centers[w * 3 + 2];
    const float R2 = (float)(0.1 * 0.1);
    const int excl = s - b * (NN - SS);

    int cnt = 0;
    for (int j0 = 0; j0 < NN && cnt < KK; j0 += 32) {
        int j = j0 + lane;
        float x_ = pb[j * 3 + 0];
        float y_ = pb[j * 3 + 1];
        float z_ = pb[j * 3 + 2];
        float dx = __fsub_rn(cx, x_);
        float dy = __fsub_rn(cy, y_);
        float dz = __fsub_rn(cz, z_);
        float d2 = __fadd_rn(__fadd_rn(__fmul_rn(dx, dx), __fmul_rn(dy, dy)),
                             __fmul_rn(dz, dz));
        bool hit = (d2 <= R2) && (j != excl);
        unsigned m = __ballot_sync(0xffffffffu, hit);
        while (m && cnt < KK) {
            int bit = __ffs(m) - 1;
            if (lane == bit) g_nbr[w * KK + cnt] = j0 + bit;
            cnt++;
            m &= m - 1;
        }
    }
    if (lane == 0) {
        g_cnt[w] = cnt;
        out_batch[w] = (float)b;
    }
}

// ===========================================================================
// Kernel 3: gather + MLP(19->64->64->128) + max over K+1 (unchanged).
// ===========================================================================
__global__ void __launch_bounds__(256, 1)
mlp_kernel(const float* __restrict__ x, const float* __restrict__ pos,
           const float* __restrict__ W1, const float* __restrict__ B1,
           const float* __restrict__ W2, const float* __restrict__ B2,
           const float* __restrict__ W3, const float* __restrict__ B3,
           float* __restrict__ out_x)
{
    extern __shared__ float sw[];
    float* sW1 = sw;
    float* sb1 = sW1 + 19 * 64;
    float* sW2 = sb1 + 64;
    float* sb2 = sW2 + 4096;
    float* sW3 = sb2 + 64;
    float* sb3 = sW3 + 8192;

    const int tid = threadIdx.x;
    for (int i = tid; i < 19 * 64; i += 256) sW1[i] = W1[i];
    for (int i = tid; i < 64;      i += 256) sb1[i] = B1[i];
    for (int i = tid; i < 64 * 64; i += 256) sW2[i] = W2[i];
    for (int i = tid; i < 64;      i += 256) sb2[i] = B2[i];
    for (int i = tid; i < 64 * 128; i += 256) sW3[i] = W3[i];
    for (int i = tid; i < 128;     i += 256) sb3[i] = B3[i];
    __syncthreads();

    const int lane = tid & 31;
    const int c    = blockIdx.x * 8 + (tid >> 5);
    const int b    = c >> 12;
    const int s    = c & (SS - 1);

    const float cx = g_centers[c * 3 + 0];
    const float cy = g_centers[c * 3 + 1];
    const float cz = g_centers[c * 3 + 2];
    const float ccomp = (lane == 16) ? cx : ((lane == 17) ? cy : cz);
    const int cnt = g_cnt[c];

    float m0 = -3.0e38f, m1 = -3.0e38f, m2 = -3.0e38f, m3 = -3.0e38f;

    auto process4 = [&](const int rows[4], int nv) {
        float fv[4];
#pragma unroll
        for (int e = 0; e < 4; e++) {
            int r = rows[e];
            float v = 0.f;
            if (lane < FIN)          v = x[(size_t)r * FIN + lane];
            else if (lane < FIN + 3) v = pos[(size_t)r * 3 + (lane - FIN)] - ccomp;
            fv[e] = (e < nv) ? v : 0.f;
        }
        float a0[4], a1[4];
#pragma unroll
        for (int e = 0; e < 4; e++) { a0[e] = sb1[lane]; a1[e] = sb1[lane + 32]; }
#pragma unroll
        for (int i = 0; i < FIN + 3; i++) {
            float w0 = sW1[i * 64 + lane];
            float w1 = sW1[i * 64 + 32 + lane];
#pragma unroll
            for (int e = 0; e < 4; e++) {
                float v = __shfl_sync(0xffffffffu, fv[e], i);
                a0[e] = fmaf(v, w0, a0[e]);
                a1[e] = fmaf(v, w1, a1[e]);
            }
        }
#pragma unroll
        for (int e = 0; e < 4; e++) { a0[e] = fmaxf(a0[e], 0.f); a1[e] = fmaxf(a1[e], 0.f); }

        float g0[4], g1[4];
#pragma unroll
        for (int e = 0; e < 4; e++) { g0[e] = sb2[lane]; g1[e] = sb2[lane + 32]; }
#pragma unroll
        for (int i = 0; i < 64; i++) {
            float w0 = sW2[i * 64 + lane];
            float w1 = sW2[i * 64 + 32 + lane];
#pragma unroll
            for (int e = 0; e < 4; e++) {
                float v = (i < 32) ? __shfl_sync(0xffffffffu, a0[e], i)
                                   : __shfl_sync(0xffffffffu, a1[e], i - 32);
                g0[e] = fmaf(v, w0, g0[e]);
                g1[e] = fmaf(v, w1, g1[e]);
            }
        }
#pragma unroll
        for (int e = 0; e < 4; e++) { g0[e] = fmaxf(g0[e], 0.f); g1[e] = fmaxf(g1[e], 0.f); }

        float h0[4], h1v[4], h2v[4], h3v[4];
#pragma unroll
        for (int e = 0; e < 4; e++) {
            h0[e]  = sb3[lane];       h1v[e] = sb3[lane + 32];
            h2v[e] = sb3[lane + 64];  h3v[e] = sb3[lane + 96];
        }
#pragma unroll
        for (int i = 0; i < 64; i++) {
            float w0 = sW3[i * 128 + lane];
            float w1 = sW3[i * 128 + 32 + lane];
            float w2 = sW3[i * 128 + 64 + lane];
            float w3 = sW3[i * 128 + 96 + lane];
#pragma unroll
            for (int e = 0; e < 4; e++) {
                float v = (i < 32) ? __shfl_sync(0xffffffffu, g0[e], i)
                                   : __shfl_sync(0xffffffffu, g1[e], i - 32);
                h0[e]  = fmaf(v, w0, h0[e]);
                h1v[e] = fmaf(v, w1, h1v[e]);
                h2v[e] = fmaf(v, w2, h2v[e]);
                h3v[e] = fmaf(v, w3, h3v[e]);
            }
        }
#pragma unroll
        for (int e = 0; e < 4; e++) {
            if (e < nv) {
                m0 = fmaxf(m0, h0[e]);  m1 = fmaxf(m1, h1v[e]);
                m2 = fmaxf(m2, h2v[e]); m3 = fmaxf(m3, h3v[e]);
            }
        }
    };

    for (int eb = 0; eb < cnt; eb += 4) {
        int nv = min(4, cnt - eb);
        int rows[4];
#pragma unroll
        for (int e = 0; e < 4; e++) {
            int kk = eb + ((e < nv) ? e : 0);
            rows[e] = b * NN + g_nbr[c * KK + kk];
        }
        process4(rows, nv);
    }
    {
        int dflat = b * SS + s;
        int rows[4] = { dflat, dflat, dflat, dflat };
        process4(rows, 1);
    }

    out_x[(size_t)c * HOUT + lane]      = m0;
    out_x[(size_t)c * HOUT + lane + 32] = m1;
    out_x[(size_t)c * HOUT + lane + 64] = m2;
    out_x[(size_t)c * HOUT + lane + 96] = m3;
}

// ===========================================================================
// launch
// ===========================================================================
extern "C" void kernel_launch(void* const* d_in, const int* in_sizes, int n_in,
                              void* d_out, int out_size)
{
    const float* x   = (const float*)d_in[0];
    const float* pos = (const float*)d_in[1];
    const float* W1 = (const float*)d_in[3];
    const float* B1 = (const float*)d_in[4];
    const float* W2 = (const float*)d_in[5];
    const float* B2 = (const float*)d_in[6];
    const float* W3 = (const float*)d_in[7];
    const float* B3 = (const float*)d_in[8];

    float* out_x = (float*)d_out;
    float* out_c = out_x + (size_t)BB * SS * HOUT;
    float* out_b = out_c + (size_t)BB * SS * 3;

    const size_t fps_smem = (size_t)3 * NN * sizeof(float);   // 192 KB dynamic
    const size_t mlp_smem = (size_t)13760 * sizeof(float);
    cudaFuncSetAttribute(fps_kernel, cudaFuncAttributeMaxDynamicSharedMemorySize, (int)fps_smem);
    cudaFuncSetAttribute(mlp_kernel, cudaFuncAttributeMaxDynamicSharedMemorySize, (int)mlp_smem);

    init_hist_kernel<<<(BB * NCELL + 255) / 256, 256>>>();
    cell_count_kernel<<<(BB * NN + 255) / 256, 256>>>(pos);
    cell_scan_kernel<<<BB, NCELL>>>();
    cell_scatter_kernel<<<(BB * NN + 255) / 256, 256>>>(pos);
    fps_kernel<<<BB, 512, fps_smem>>>(pos, out_c);
    ballq_kernel<<<(BB * SS * 32) / 256, 256>>>(pos, out_b);
    mlp_kernel<<<(BB * SS) / 8, 256, mlp_smem>>>(x, pos, W1, B1, W2, B2, W3, B3, out_x);
}

// round 12
// speedup vs baseline: 1.0120x; 1.0120x over previous
#include <cuda_runtime.h>
#include <cstdint>

// ---------------------------------------------------------------------------
// SetAbstraction (PointNet++): FPS -> ball query -> MLP -> max
// B=2, N=16384, S=4096, K=32, F_IN=16, hidden 64-64-128
// Round 12 FPS: R10 (XOR remap, packed REDUX, single barrier, z via L1-hot
// lookup) with:
//   - point data fused into ONE float4 (x,y,z,idx) -> single LDG.128 per
//     chunk; smem shrinks to dmin only (64KB) so L1 carveout grows ~4.5x
//   - (st,len) packed into one word -> single shfl per cell
// Selection sequence bit-identical to the naive scan.
// ---------------------------------------------------------------------------

#define BB   2
#define NN   16384
#define SS   4096
#define KK   32
#define FIN  16
#define HOUT 128
#define GC    8
#define NCELL 512
#define CW    0.125f
#define FULLM 0xffffffffu

// ---- scratch (__device__ globals; no allocation allowed) -------------------
__device__ float g_centers[BB * SS * 3];
__device__ int   g_nbr[BB * SS * KK];
__device__ int   g_cnt[BB * SS];

__device__ float4 g_pt4[BB * NN];      // sorted (x, y, z, origidx-bits)
__device__ int    g_hist[BB * NCELL];
__device__ int    g_cstart[BB * (NCELL + 1)];
__device__ int    g_fill[BB * NCELL];

__device__ __forceinline__ int cell_of(float x, float y, float z) {
    int ix = (int)(x * (float)GC); ix = ix < 0 ? 0 : (ix > GC - 1 ? GC - 1 : ix);
    int iy = (int)(y * (float)GC); iy = iy < 0 ? 0 : (iy > GC - 1 ? GC - 1 : iy);
    int iz = (int)(z * (float)GC); iz = iz < 0 ? 0 : (iz > GC - 1 ? GC - 1 : iz);
    return (iz * GC + iy) * GC + ix;
}

// ===========================================================================
// Preprocessing: histogram -> scan -> scatter (counting sort by cell)
// ===========================================================================
__global__ void init_hist_kernel() {
    int i = blockIdx.x * blockDim.x + threadIdx.x;
    if (i < BB * NCELL) g_hist[i] = 0;
}

__global__ void cell_count_kernel(const float* __restrict__ pos) {
    int i = blockIdx.x * blockDim.x + threadIdx.x;
    if (i >= BB * NN) return;
    int b = i >> 14;
    float x = pos[(size_t)i * 3 + 0], y = pos[(size_t)i * 3 + 1], z = pos[(size_t)i * 3 + 2];
    atomicAdd(&g_hist[b * NCELL + cell_of(x, y, z)], 1);
}

__global__ void cell_scan_kernel() {
    __shared__ int sh[NCELL];
    __shared__ int ss[NCELL + 1];
    int b = blockIdx.x, tid = threadIdx.x;
    if (tid < NCELL) sh[tid] = g_hist[b * NCELL + tid];
    __syncthreads();
    if (tid == 0) {
        int acc = 0;
        for (int c = 0; c < NCELL; c++) { ss[c] = acc; acc += sh[c]; }
        ss[NCELL] = acc;
    }
    __syncthreads();
    if (tid < NCELL) {
        g_cstart[b * (NCELL + 1) + tid] = ss[tid];
        g_fill[b * NCELL + tid] = ss[tid];
    }
    if (tid == 0) g_cstart[b * (NCELL + 1) + NCELL] = ss[NCELL];
}

__global__ void cell_scatter_kernel(const float* __restrict__ pos) {
    int i = blockIdx.x * blockDim.x + threadIdx.x;
    if (i >= BB * NN) return;
    int b = i >> 14;
    int li = i & (NN - 1);
    float x = pos[(size_t)i * 3 + 0], y = pos[(size_t)i * 3 + 1], z = pos[(size_t)i * 3 + 2];
    int c = cell_of(x, y, z);
    int p = atomicAdd(&g_fill[b * NCELL + c], 1);
    g_pt4[b * NN + p] = make_float4(x, y, z, __int_as_float(li));
}

// ===========================================================================
// Kernel 1: grid-pruned exact FPS. One block per batch, 512 threads (16 warps).
// Cell assignment: p = w + 16*lane, cell = p ^ ((p>>6)*9)  (XOR bijection).
// Per-lane scan key u64 = (dmin_bits<<28)|(~origidx&0x3fff)<<14|sorted_pos.
// ONE __syncthreads per iteration (double-buffered partials). Point data =
// single float4 LDG.128; smem holds only dmin (64KB) -> big L1 carveout.
// ===========================================================================
__global__ void __launch_bounds__(512, 1)
fps_kernel(const float* __restrict__ pos, float* __restrict__ out_centers)
{
    extern __shared__ float sm[];
    float* s_dmin = sm;                  // NN floats (64 KB)

    __shared__ unsigned long long s_part[2][16];  // parity-buffered partials

    const int b = blockIdx.x, tid = threadIdx.x;
    const int w = tid >> 5, lane = tid & 31;
    const int base = b * NN;
    const float4* __restrict__ gp4 = g_pt4 + base;

    for (int p = tid; p < NN; p += 512) s_dmin[p] = 1e10f;
    if (tid < 16) { s_part[0][tid] = 0ULL; s_part[1][tid] = 0ULL; }

    // this lane's owned cell (XOR bijection spreads x, y AND z neighbors)
    const int pidx = w + (lane << 4);
    const int cell = pidx ^ ((pidx >> 6) * 9);
    const int cs0 = g_cstart[b * (NCELL + 1) + cell];
    const int len = g_cstart[b * (NCELL + 1) + cell + 1] - cs0;
    const unsigned cspack = (unsigned)cs0 | ((unsigned)len << 15);   // st:15 | len:17
    const int ix = cell & 7, iy = (cell >> 3) & 7, iz = cell >> 6;
    const float lox = (float)ix * CW - 1e-5f, hix = (float)ix * CW + CW + 1e-5f;
    const float loy = (float)iy * CW - 1e-5f, hiy = (float)iy * CW + CW + 1e-5f;
    const float loz = (float)iz * CW - 1e-5f, hiz = (float)iz * CW + CW + 1e-5f;

    unsigned kv    = __float_as_uint(1e10f);   // cached cell key: max dmin bits
    unsigned kcand = 0u;                       // (lo14<<14)|p of winner

    // initial center (deterministic start at original point 0), in registers
    float cx = pos[(size_t)base * 3 + 0];
    float cy = pos[(size_t)base * 3 + 1];
    float cz = pos[(size_t)base * 3 + 2];
    if (tid == 0) {
        int row = b * SS;
        out_centers[row * 3 + 0] = cx; out_centers[row * 3 + 1] = cy; out_centers[row * 3 + 2] = cz;
        g_centers[row * 3 + 0]   = cx; g_centers[row * 3 + 1]   = cy; g_centers[row * 3 + 2]   = cz;
    }
    __syncthreads();

    for (int t = 1; t < SS; t++) {
        const int par = t & 1;

        // --- prune: each lane checks its own cell --------------------------
        float pdx = fmaxf(fmaxf(lox - cx, cx - hix), 0.f);
        float pdy = fmaxf(fmaxf(loy - cy, cy - hiy), 0.f);
        float pdz = fmaxf(fmaxf(loz - cz, cz - hiz), 0.f);
        float lb  = (pdx * pdx + pdy * pdy + pdz * pdz) * 0.999f;
        bool touched = lb < __uint_as_float(kv);
        unsigned tmask = __ballot_sync(FULLM, touched);

        if (tmask) {
            // --- process touched cells (pipelined next-cell preload) -------
            int j = __ffs(tmask) - 1; tmask &= tmask - 1;
            unsigned sp = __shfl_sync(FULLM, cspack, j);
            int st = (int)(sp & 0x7fffu);
            int en = st + (int)(sp >> 15);
            int p0v = st + lane; bool v = p0v < en;
            float4 pt = make_float4(0.f, 0.f, 0.f, 0.f);
            if (v) pt = gp4[p0v];
            if (st + 32 + lane < en) {
                const float4* pf = &gp4[st + 32 + lane];
                asm volatile("prefetch.global.L1 [%0];" :: "l"(pf));
            }
            while (j >= 0) {
                unsigned long long best = 0ULL;
                if (v) {
                    int p = st + lane;
                    float ddx = __fsub_rn(pt.x, cx);
                    float ddy = __fsub_rn(pt.y, cy);
                    float ddz = __fsub_rn(pt.z, cz);
                    float d   = __fadd_rn(__fadd_rn(__fmul_rn(ddx, ddx), __fmul_rn(ddy, ddy)),
                                          __fmul_rn(ddz, ddz));
                    float dm  = fminf(s_dmin[p], d);
                    s_dmin[p] = dm;
                    unsigned lo14 = (~(unsigned)__float_as_int(pt.w)) & 0x3fffu;
                    best = (((unsigned long long)__float_as_uint(dm)) << 28)
                         | ((unsigned long long)lo14 << 14)
                         | (unsigned long long)p;
                }
                // preload next touched cell's first chunk
                int jn = -1, stn = 0, enn = 0; bool vn = false;
                float4 ptn = make_float4(0.f, 0.f, 0.f, 0.f);
                if (tmask) {
                    jn = __ffs(tmask) - 1; tmask &= tmask - 1;
                    unsigned spn = __shfl_sync(FULLM, cspack, jn);
                    stn = (int)(spn & 0x7fffu);
                    enn = stn + (int)(spn >> 15);
                    int p = stn + lane; vn = p < enn;
                    if (vn) ptn = gp4[p];
                    if (stn + 32 + lane < enn) {
                        const float4* pf = &gp4[stn + 32 + lane];
                        asm volatile("prefetch.global.L1 [%0];" :: "l"(pf));
                    }
                }
                // remaining chunks of current cell
                for (int pp = st + 32; pp < en; pp += 32) {
                    int p = pp + lane;
                    if (p < en) {
                        float4 p2 = gp4[p];
                        float ddx = __fsub_rn(p2.x, cx);
                        float ddy = __fsub_rn(p2.y, cy);
                        float ddz = __fsub_rn(p2.z, cz);
                        float d   = __fadd_rn(__fadd_rn(__fmul_rn(ddx, ddx), __fmul_rn(ddy, ddy)),
                                              __fmul_rn(ddz, ddz));
                        float dm  = fminf(s_dmin[p], d);
                        s_dmin[p] = dm;
                        unsigned lo14 = (~(unsigned)__float_as_int(p2.w)) & 0x3fffu;
                        unsigned long long pk =
                            (((unsigned long long)__float_as_uint(dm)) << 28)
                            | ((unsigned long long)lo14 << 14)
                            | (unsigned long long)p;
                        if (pk > best) best = pk;
                    }
                }
                // cell key via packed REDUX (identity rides in the value)
                unsigned du    = (unsigned)(best >> 28);
                unsigned wm    = __reduce_max_sync(FULLM, du);
                unsigned cand  = (du == wm) ? (unsigned)(best & 0xFFFFFFFull) : 0u;
                unsigned mcand = __reduce_max_sync(FULLM, cand);
                if (lane == j) { kv = wm; kcand = mcand; }
                j = jn; st = stn; en = enn; v = vn; pt = ptn;
            }

            // per-warp partial over its 32 owned cells -> parity buffer
            unsigned mv  = __reduce_max_sync(FULLM, kv);
            unsigned c2  = (kv == mv) ? kcand : 0u;
            unsigned mc2 = __reduce_max_sync(FULLM, c2);
            if (kv == mv && kcand == mc2) {   // unique (mc2 embeds unique p)
                s_part[par][w] = (((unsigned long long)mv) << 32) | mc2;
            }
        } else {
            // untouched warp: partial unchanged; copy across parity
            if (lane == 0) s_part[par][w] = s_part[par ^ 1][w];
        }
        __syncthreads();   // the ONLY barrier per iteration

        // --- redundant final argmax over 16 partials (every warp) ----------
        unsigned long long pk = (lane < 16) ? s_part[par][lane] : 0ULL;
        unsigned hi = (unsigned)(pk >> 32), lo = (unsigned)pk;
        unsigned mv2 = __reduce_max_sync(FULLM, hi);
        unsigned c3  = (hi == mv2) ? lo : 0u;
        unsigned mc3 = __reduce_max_sync(FULLM, c3);
        int wp  = (int)(mc3 & 0x3fffu);
        float4 win = gp4[wp];                        // uniform LDG.128, L1-hot
        cx = win.x; cy = win.y; cz = win.z;          // next center, in regs
        if (w == 0 && hi == mv2 && lo == mc3) {      // unique winner lane
            int row = b * SS + t;
            out_centers[row * 3 + 0] = cx; out_centers[row * 3 + 1] = cy; out_centers[row * 3 + 2] = cz;
            g_centers[row * 3 + 0]   = cx; g_centers[row * 3 + 1]   = cy; g_centers[row * 3 + 2]   = cz;
        }
    }
}

// ===========================================================================
// Kernel 2: Ball query — one warp per center; ordered scan, first K within R.
// ===========================================================================
__global__ void __launch_bounds__(256, 8)
ballq_kernel(const float* __restrict__ pos, float* __restrict__ out_batch)
{
    const int w    = (blockIdx.x * blockDim.x + threadIdx.x) >> 5;
    const int lane = threadIdx.x & 31;
    if (w >= BB * SS) return;

    const int b = w >> 12;
    const int s = w & (SS - 1);
    const float* pb = pos + (size_t)b * NN * 3;

    const float cx = g_centers[w * 3 + 0];
    const float cy = g_centers[w * 3 + 1];
    const float cz = g_centers[w * 3 + 2];
    const float R2 = (float)(0.1 * 0.1);
    const int excl = s - b * (NN - SS);

    int cnt = 0;
    for (int j0 = 0; j0 < NN && cnt < KK; j0 += 32) {
        int j = j0 + lane;
        float x_ = pb[j * 3 + 0];
        float y_ = pb[j * 3 + 1];
        float z_ = pb[j * 3 + 2];
        float dx = __fsub_rn(cx, x_);
        float dy = __fsub_rn(cy, y_);
        float dz = __fsub_rn(cz, z_);
        float d2 = __fadd_rn(__fadd_rn(__fmul_rn(dx, dx), __fmul_rn(dy, dy)),
                             __fmul_rn(dz, dz));
        bool hit = (d2 <= R2) && (j != excl);
        unsigned m = __ballot_sync(0xffffffffu, hit);
        while (m && cnt < KK) {
            int bit = __ffs(m) - 1;
            if (lane == bit) g_nbr[w * KK + cnt] = j0 + bit;
            cnt++;
            m &= m - 1;
        }
    }
    if (lane == 0) {
        g_cnt[w] = cnt;
        out_batch[w] = (float)b;
    }
}

// ===========================================================================
// Kernel 3: gather + MLP(19->64->64->128) + max over K+1 (unchanged).
// ===========================================================================
__global__ void __launch_bounds__(256, 1)
mlp_kernel(const float* __restrict__ x, const float* __restrict__ pos,
           const float* __restrict__ W1, const float* __restrict__ B1,
           const float* __restrict__ W2, const float* __restrict__ B2,
           const float* __restrict__ W3, const float* __restrict__ B3,
           float* __restrict__ out_x)
{
    extern __shared__ float sw[];
    float* sW1 = sw;
    float* sb1 = sW1 + 19 * 64;
    float* sW2 = sb1 + 64;
    float* sb2 = sW2 + 4096;
    float* sW3 = sb2 + 64;
    float* sb3 = sW3 + 8192;

    const int tid = threadIdx.x;
    for (int i = tid; i < 19 * 64; i += 256) sW1[i] = W1[i];
    for (int i = tid; i < 64;      i += 256) sb1[i] = B1[i];
    for (int i = tid; i < 64 * 64; i += 256) sW2[i] = W2[i];
    for (int i = tid; i < 64;      i += 256) sb2[i] = B2[i];
    for (int i = tid; i < 64 * 128; i += 256) sW3[i] = W3[i];
    for (int i = tid; i < 128;     i += 256) sb3[i] = B3[i];
    __syncthreads();

    const int lane = tid & 31;
    const int c    = blockIdx.x * 8 + (tid >> 5);
    const int b    = c >> 12;
    const int s    = c & (SS - 1);

    const float cx = g_centers[c * 3 + 0];
    const float cy = g_centers[c * 3 + 1];
    const float cz = g_centers[c * 3 + 2];
    const float ccomp = (lane == 16) ? cx : ((lane == 17) ? cy : cz);
    const int cnt = g_cnt[c];

    float m0 = -3.0e38f, m1 = -3.0e38f, m2 = -3.0e38f, m3 = -3.0e38f;

    auto process4 = [&](const int rows[4], int nv) {
        float fv[4];
#pragma unroll
        for (int e = 0; e < 4; e++) {
            int r = rows[e];
            float v = 0.f;
            if (lane < FIN)          v = x[(size_t)r * FIN + lane];
            else if (lane < FIN + 3) v = pos[(size_t)r * 3 + (lane - FIN)] - ccomp;
            fv[e] = (e < nv) ? v : 0.f;
        }
        float a0[4], a1[4];
#pragma unroll
        for (int e = 0; e < 4; e++) { a0[e] = sb1[lane]; a1[e] = sb1[lane + 32]; }
#pragma unroll
        for (int i = 0; i < FIN + 3; i++) {
            float w0 = sW1[i * 64 + lane];
            float w1 = sW1[i * 64 + 32 + lane];
#pragma unroll
            for (int e = 0; e < 4; e++) {
                float v = __shfl_sync(0xffffffffu, fv[e], i);
                a0[e] = fmaf(v, w0, a0[e]);
                a1[e] = fmaf(v, w1, a1[e]);
            }
        }
#pragma unroll
        for (int e = 0; e < 4; e++) { a0[e] = fmaxf(a0[e], 0.f); a1[e] = fmaxf(a1[e], 0.f); }

        float g0[4], g1[4];
#pragma unroll
        for (int e = 0; e < 4; e++) { g0[e] = sb2[lane]; g1[e] = sb2[lane + 32]; }
#pragma unroll
        for (int i = 0; i < 64; i++) {
            float w0 = sW2[i * 64 + lane];
            float w1 = sW2[i * 64 + 32 + lane];
#pragma unroll
            for (int e = 0; e < 4; e++) {
                float v = (i < 32) ? __shfl_sync(0xffffffffu, a0[e], i)
                                   : __shfl_sync(0xffffffffu, a1[e], i - 32);
                g0[e] = fmaf(v, w0, g0[e]);
                g1[e] = fmaf(v, w1, g1[e]);
            }
        }
#pragma unroll
        for (int e = 0; e < 4; e++) { g0[e] = fmaxf(g0[e], 0.f); g1[e] = fmaxf(g1[e], 0.f); }

        float h0[4], h1v[4], h2v[4], h3v[4];
#pragma unroll
        for (int e = 0; e < 4; e++) {
            h0[e]  = sb3[lane];       h1v[e] = sb3[lane + 32];
            h2v[e] = sb3[lane + 64];  h3v[e] = sb3[lane + 96];
        }
#pragma unroll
        for (int i = 0; i < 64; i++) {
            float w0 = sW3[i * 128 + lane];
            float w1 = sW3[i * 128 + 32 + lane];
            float w2 = sW3[i * 128 + 64 + lane];
            float w3 = sW3[i * 128 + 96 + lane];
#pragma unroll
            for (int e = 0; e < 4; e++) {
                float v = (i < 32) ? __shfl_sync(0xffffffffu, g0[e], i)
                                   : __shfl_sync(0xffffffffu, g1[e], i - 32);
                h0[e]  = fmaf(v, w0, h0[e]);
                h1v[e] = fmaf(v, w1, h1v[e]);
                h2v[e] = fmaf(v, w2, h2v[e]);
                h3v[e] = fmaf(v, w3, h3v[e]);
            }
        }
#pragma unroll
        for (int e = 0; e < 4; e++) {
            if (e < nv) {
                m0 = fmaxf(m0, h0[e]);  m1 = fmaxf(m1, h1v[e]);
                m2 = fmaxf(m2, h2v[e]); m3 = fmaxf(m3, h3v[e]);
            }
        }
    };

    for (int eb = 0; eb < cnt; eb += 4) {
        int nv = min(4, cnt - eb);
        int rows[4];
#pragma unroll
        for (int e = 0; e < 4; e++) {
            int kk = eb + ((e < nv) ? e : 0);
            rows[e] = b * NN + g_nbr[c * KK + kk];
        }
        process4(rows, nv);
    }
    {
        int dflat = b * SS + s;
        int rows[4] = { dflat, dflat, dflat, dflat };
        process4(rows, 1);
    }

    out_x[(size_t)c * HOUT + lane]      = m0;
    out_x[(size_t)c * HOUT + lane + 32] = m1;
    out_x[(size_t)c * HOUT + lane + 64] = m2;
    out_x[(size_t)c * HOUT + lane + 96] = m3;
}

// ===========================================================================
// launch
// ===========================================================================
extern "C" void kernel_launch(void* const* d_in, const int* in_sizes, int n_in,
                              void* d_out, int out_size)
{
    const float* x   = (const float*)d_in[0];
    const float* pos = (const float*)d_in[1];
    const float* W1 = (const float*)d_in[3];
    const float* B1 = (const float*)d_in[4];
    const float* W2 = (const float*)d_in[5];
    const float* B2 = (const float*)d_in[6];
    const float* W3 = (const float*)d_in[7];
    const float* B3 = (const float*)d_in[8];

    float* out_x = (float*)d_out;
    float* out_c = out_x + (size_t)BB * SS * HOUT;
    float* out_b = out_c + (size_t)BB * SS * 3;

    const size_t fps_smem = (size_t)NN * sizeof(float);       // 64 KB dynamic
    const size_t mlp_smem = (size_t)13760 * sizeof(float);
    cudaFuncSetAttribute(fps_kernel, cudaFuncAttributeMaxDynamicSharedMemorySize, (int)fps_smem);
    cudaFuncSetAttribute(mlp_kernel, cudaFuncAttributeMaxDynamicSharedMemorySize, (int)mlp_smem);

    init_hist_kernel<<<(BB * NCELL + 255) / 256, 256>>>();
    cell_count_kernel<<<(BB * NN + 255) / 256, 256>>>(pos);
    cell_scan_kernel<<<BB, NCELL>>>();
    cell_scatter_kernel<<<(BB * NN + 255) / 256, 256>>>(pos);
    fps_kernel<<<BB, 512, fps_smem>>>(pos, out_c);
    ballq_kernel<<<(BB * SS * 32) / 256, 256>>>(pos, out_b);
    mlp_kernel<<<(BB * SS) / 8, 256, mlp_smem>>>(x, pos, W1, B1, W2, B2, W3, B3, out_x);
}

// round 13
// speedup vs baseline: 1.1375x; 1.1241x over previous
#include <cuda_runtime.h>
#include <cstdint>

// ---------------------------------------------------------------------------
// SetAbstraction (PointNet++): FPS -> ball query -> MLP -> max
// B=2, N=16384, S=4096, K=32, F_IN=16, hidden 64-64-128
// Round 13 FPS: R10 skeleton (LDS xy + LDG z/idx, packed REDUX, single
// barrier, register center, L1-hot winner lookup) with PRUNE UNITS = fixed
// 32-point slices of the cell-sorted array:
//   - 512 slices x exactly 32 points; per-slice exact AABB (one-time init)
//   - slice start computable -> no per-cell shfl, no inner loop, no ragged
//     tails; uniform per-unit cost -> smaller barrier skew
// Selection sequence bit-identical to the naive scan.
// ---------------------------------------------------------------------------

#define BB   2
#define NN   16384
#define SS   4096
#define KK   32
#define FIN  16
#define HOUT 128
#define GC    8
#define NCELL 512
#define NSLICE 512
#define FULLM 0xffffffffu

// ---- scratch (__device__ globals; no allocation allowed) -------------------
__device__ float g_centers[BB * SS * 3];
__device__ int   g_nbr[BB * SS * KK];
__device__ int   g_cnt[BB * SS];

__device__ float2 g_sxy[BB * NN];      // sorted (x,y)
__device__ int2   g_szi[BB * NN];      // sorted (z bits, orig idx)
__device__ int    g_hist[BB * NCELL];
__device__ int    g_cstart[BB * (NCELL + 1)];
__device__ int    g_fill[BB * NCELL];

__device__ __forceinline__ int cell_of(float x, float y, float z) {
    int ix = (int)(x * (float)GC); ix = ix < 0 ? 0 : (ix > GC - 1 ? GC - 1 : ix);
    int iy = (int)(y * (float)GC); iy = iy < 0 ? 0 : (iy > GC - 1 ? GC - 1 : iy);
    int iz = (int)(z * (float)GC); iz = iz < 0 ? 0 : (iz > GC - 1 ? GC - 1 : iz);
    return (iz * GC + iy) * GC + ix;
}

// ===========================================================================
// Preprocessing: histogram -> scan -> scatter (counting sort by cell)
// ===========================================================================
__global__ void init_hist_kernel() {
    int i = blockIdx.x * blockDim.x + threadIdx.x;
    if (i < BB * NCELL) g_hist[i] = 0;
}

__global__ void cell_count_kernel(const float* __restrict__ pos) {
    int i = blockIdx.x * blockDim.x + threadIdx.x;
    if (i >= BB * NN) return;
    int b = i >> 14;
    float x = pos[(size_t)i * 3 + 0], y = pos[(size_t)i * 3 + 1], z = pos[(size_t)i * 3 + 2];
    atomicAdd(&g_hist[b * NCELL + cell_of(x, y, z)], 1);
}

__global__ void cell_scan_kernel() {
    __shared__ int sh[NCELL];
    __shared__ int ss[NCELL + 1];
    int b = blockIdx.x, tid = threadIdx.x;
    if (tid < NCELL) sh[tid] = g_hist[b * NCELL + tid];
    __syncthreads();
    if (tid == 0) {
        int acc = 0;
        for (int c = 0; c < NCELL; c++) { ss[c] = acc; acc += sh[c]; }
        ss[NCELL] = acc;
    }
    __syncthreads();
    if (tid < NCELL) {
        g_cstart[b * (NCELL + 1) + tid] = ss[tid];
        g_fill[b * NCELL + tid] = ss[tid];
    }
    if (tid == 0) g_cstart[b * (NCELL + 1) + NCELL] = ss[NCELL];
}

__global__ void cell_scatter_kernel(const float* __restrict__ pos) {
    int i = blockIdx.x * blockDim.x + threadIdx.x;
    if (i >= BB * NN) return;
    int b = i >> 14;
    int li = i & (NN - 1);
    float x = pos[(size_t)i * 3 + 0], y = pos[(size_t)i * 3 + 1], z = pos[(size_t)i * 3 + 2];
    int c = cell_of(x, y, z);
    int p = atomicAdd(&g_fill[b * NCELL + c], 1);
    g_sxy[b * NN + p] = make_float2(x, y);
    g_szi[b * NN + p] = make_int2(__float_as_int(z), li);
}

// ===========================================================================
// Kernel 1: slice-pruned exact FPS. One block per batch, 512 threads (16 warps).
// Slice sl = w + 16*lane (adjacent slices -> distinct warps); st = sl*32.
// Per-lane scan key u64 = (dmin_bits<<28)|(~origidx&0x3fff)<<14|sorted_pos.
// ONE __syncthreads per iteration (double-buffered partials).
// ===========================================================================
__global__ void __launch_bounds__(512, 1)
fps_kernel(const float* __restrict__ pos, float* __restrict__ out_centers)
{
    extern __shared__ float sm[];
    float2* s_xy   = (float2*)sm;        // NN float2 (128 KB)
    float*  s_dmin = sm + 2 * NN;        // NN floats (64 KB)

    __shared__ unsigned long long s_part[2][16];  // parity-buffered partials

    const int b = blockIdx.x, tid = threadIdx.x;
    const int w = tid >> 5, lane = tid & 31;
    const int base = b * NN;
    const int2* __restrict__ gz = g_szi + base;

    for (int p = tid; p < NN; p += 512) {
        s_xy[p] = g_sxy[base + p];
        s_dmin[p] = 1e10f;
    }
    if (tid < 16) { s_part[0][tid] = 0ULL; s_part[1][tid] = 0ULL; }
    __syncthreads();

    // --- one-time per-slice AABB (cooperative: 6 REDUX per slice) ----------
    // this lane owns slice sl = w + 16*lane, st_own = sl*32
    const int st_own = (w << 5) + (lane << 9);
    float lox, hix, loy, hiy, loz, hiz;
    for (int j = 0; j < 32; j++) {
        int st = (w << 5) + (j << 9);
        int p = st + lane;
        float2 xy = s_xy[p];
        float  zz = __int_as_float(gz[p].x);
        // coords are in [0,1): nonneg float bits are value-monotonic
        unsigned mnx = __reduce_min_sync(FULLM, __float_as_uint(xy.x));
        unsigned mxx = __reduce_max_sync(FULLM, __float_as_uint(xy.x));
        unsigned mny = __reduce_min_sync(FULLM, __float_as_uint(xy.y));
        unsigned mxy = __reduce_max_sync(FULLM, __float_as_uint(xy.y));
        unsigned mnz = __reduce_min_sync(FULLM, __float_as_uint(zz));
        unsigned mxz = __reduce_max_sync(FULLM, __float_as_uint(zz));
        if (lane == j) {
            lox = __uint_as_float(mnx) - 1e-5f; hix = __uint_as_float(mxx) + 1e-5f;
            loy = __uint_as_float(mny) - 1e-5f; hiy = __uint_as_float(mxy) + 1e-5f;
            loz = __uint_as_float(mnz) - 1e-5f; hiz = __uint_as_float(mxz) + 1e-5f;
        }
    }

    unsigned kv    = __float_as_uint(1e10f);   // cached slice key: max dmin bits
    unsigned kcand = 0u;                       // (lo14<<14)|p of winner

    // initial center (deterministic start at original point 0), in registers
    float cx = pos[(size_t)base * 3 + 0];
    float cy = pos[(size_t)base * 3 + 1];
    float cz = pos[(size_t)base * 3 + 2];
    if (tid == 0) {
        int row = b * SS;
        out_centers[row * 3 + 0] = cx; out_centers[row * 3 + 1] = cy; out_centers[row * 3 + 2] = cz;
        g_centers[row * 3 + 0]   = cx; g_centers[row * 3 + 1]   = cy; g_centers[row * 3 + 2]   = cz;
    }
    __syncthreads();

    for (int t = 1; t < SS; t++) {
        const int par = t & 1;

        // --- prune: each lane checks its own slice AABB ---------------------
        float pdx = fmaxf(fmaxf(lox - cx, cx - hix), 0.f);
        float pdy = fmaxf(fmaxf(loy - cy, cy - hiy), 0.f);
        float pdz = fmaxf(fmaxf(loz - cz, cz - hiz), 0.f);
        float lb  = (pdx * pdx + pdy * pdy + pdz * pdz) * 0.999f;
        bool touched = lb < __uint_as_float(kv);

        // self-prefetch own slice's two z/idx lines (fire-and-forget)
        if (touched) {
            const int2* pf0 = &gz[st_own];
            asm volatile("prefetch.global.L1 [%0];" :: "l"(pf0));
            const int2* pf1 = &gz[st_own + 16];
            asm volatile("prefetch.global.L1 [%0];" :: "l"(pf1));
        }
        unsigned tmask = __ballot_sync(FULLM, touched);

        if (tmask) {
            // --- process touched slices (1 chunk each, pipelined preload) --
            int j = __ffs(tmask) - 1; tmask &= tmask - 1;
            int st = (w << 5) + (j << 9);
            int p  = st + lane;
            int2 zi = gz[p];
            float2 xy = s_xy[p];
            while (j >= 0) {
                float zz  = __int_as_float(zi.x);
                float ddx = __fsub_rn(xy.x, cx);
                float ddy = __fsub_rn(xy.y, cy);
                float ddz = __fsub_rn(zz,   cz);
                float d   = __fadd_rn(__fadd_rn(__fmul_rn(ddx, ddx), __fmul_rn(ddy, ddy)),
                                      __fmul_rn(ddz, ddz));
                float dm  = fminf(s_dmin[p], d);
                s_dmin[p] = dm;
                unsigned lo14 = (~(unsigned)zi.y) & 0x3fffu;
                unsigned long long best =
                    (((unsigned long long)__float_as_uint(dm)) << 28)
                    | ((unsigned long long)lo14 << 14)
                    | (unsigned long long)p;

                // preload next touched slice
                int jn = -1, pn = 0;
                int2 zin = make_int2(0, 0); float2 xyn = make_float2(0.f, 0.f);
                if (tmask) {
                    jn = __ffs(tmask) - 1; tmask &= tmask - 1;
                    pn = (w << 5) + (jn << 9) + lane;
                    zin = gz[pn]; xyn = s_xy[pn];
                }

                // slice key via packed REDUX (identity rides in the value)
                unsigned du    = (unsigned)(best >> 28);
                unsigned wm    = __reduce_max_sync(FULLM, du);
                unsigned cand  = (du == wm) ? (unsigned)(best & 0xFFFFFFFull) : 0u;
                unsigned mcand = __reduce_max_sync(FULLM, cand);
                if (lane == j) { kv = wm; kcand = mcand; }
                j = jn; p = pn; zi = zin; xy = xyn;
            }

            // per-warp partial over its 32 owned slices -> parity buffer
            unsigned mv  = __reduce_max_sync(FULLM, kv);
            unsigned c2  = (kv == mv) ? kcand : 0u;
            unsigned mc2 = __reduce_max_sync(FULLM, c2);
            if (kv == mv && kcand == mc2) {   // unique (mc2 embeds unique p)
                s_part[par][w] = (((unsigned long long)mv) << 32) | mc2;
            }
        } else {
            // untouched warp: partial unchanged; copy across parity
            if (lane == 0) s_part[par][w] = s_part[par ^ 1][w];
        }
        __syncthreads();   // the ONLY barrier per iteration

        // --- redundant final argmax over 16 partials (every warp) ----------
        unsigned long long pk = (lane < 16) ? s_part[par][lane] : 0ULL;
        unsigned hi = (unsigned)(pk >> 32), lo = (unsigned)pk;
        unsigned mv2 = __reduce_max_sync(FULLM, hi);
        unsigned c3  = (hi == mv2) ? lo : 0u;
        unsigned mc3 = __reduce_max_sync(FULLM, c3);
        int wp  = (int)(mc3 & 0x3fffu);
        float2 xyw = s_xy[wp];                       // broadcast LDS
        float  zw  = __int_as_float(gz[wp].x);       // uniform LDG, L1-hot
        cx = xyw.x; cy = xyw.y; cz = zw;             // next center, in regs
        if (w == 0 && hi == mv2 && lo == mc3) {      // unique winner lane
            int row = b * SS + t;
            out_centers[row * 3 + 0] = cx; out_centers[row * 3 + 1] = cy; out_centers[row * 3 + 2] = cz;
            g_centers[row * 3 + 0]   = cx; g_centers[row * 3 + 1]   = cy; g_centers[row * 3 + 2]   = cz;
        }
    }
}

// ===========================================================================
// Kernel 2: Ball query — one warp per center; ordered scan, first K within R.
// ===========================================================================
__global__ void __launch_bounds__(256, 8)
ballq_kernel(const float* __restrict__ pos, float* __restrict__ out_batch)
{
    const int w    = (blockIdx.x * blockDim.x + threadIdx.x) >> 5;
    const int lane = threadIdx.x & 31;
    if (w >= BB * SS) return;

    const int b = w >> 12;
    const int s = w & (SS - 1);
    const float* pb = pos + (size_t)b * NN * 3;

    const float cx = g_centers[w * 3 + 0];
    const float cy = g_centers[w * 3 + 1];
    const float cz = g_centers[w * 3 + 2];
    const float R2 = (float)(0.1 * 0.1);
    const int excl = s - b * (NN - SS);

    int cnt = 0;
    for (int j0 = 0; j0 < NN && cnt < KK; j0 += 32) {
        int j = j0 + lane;
        float x_ = pb[j * 3 + 0];
        float y_ = pb[j * 3 + 1];
        float z_ = pb[j * 3 + 2];
        float dx = __fsub_rn(cx, x_);
        float dy = __fsub_rn(cy, y_);
        float dz = __fsub_rn(cz, z_);
        float d2 = __fadd_rn(__fadd_rn(__fmul_rn(dx, dx), __fmul_rn(dy, dy)),
                             __fmul_rn(dz, dz));
        bool hit = (d2 <= R2) && (j != excl);
        unsigned m = __ballot_sync(0xffffffffu, hit);
        while (m && cnt < KK) {
            int bit = __ffs(m) - 1;
            if (lane == bit) g_nbr[w * KK + cnt] = j0 + bit;
            cnt++;
            m &= m - 1;
        }
    }
    if (lane == 0) {
        g_cnt[w] = cnt;
        out_batch[w] = (float)b;
    }
}

// ===========================================================================
// Kernel 3: gather + MLP(19->64->64->128) + max over K+1 (unchanged).
// ===========================================================================
__global__ void __launch_bounds__(256, 1)
mlp_kernel(const float* __restrict__ x, const float* __restrict__ pos,
           const float* __restrict__ W1, const float* __restrict__ B1,
           const float* __restrict__ W2, const float* __restrict__ B2,
           const float* __restrict__ W3, const float* __restrict__ B3,
           float* __restrict__ out_x)
{
    extern __shared__ float sw[];
    float* sW1 = sw;
    float* sb1 = sW1 + 19 * 64;
    float* sW2 = sb1 + 64;
    float* sb2 = sW2 + 4096;
    float* sW3 = sb2 + 64;
    float* sb3 = sW3 + 8192;

    const int tid = threadIdx.x;
    for (int i = tid; i < 19 * 64; i += 256) sW1[i] = W1[i];
    for (int i = tid; i < 64;      i += 256) sb1[i] = B1[i];
    for (int i = tid; i < 64 * 64; i += 256) sW2[i] = W2[i];
    for (int i = tid; i < 64;      i += 256) sb2[i] = B2[i];
    for (int i = tid; i < 64 * 128; i += 256) sW3[i] = W3[i];
    for (int i = tid; i < 128;     i += 256) sb3[i] = B3[i];
    __syncthreads();

    const int lane = tid & 31;
    const int c    = blockIdx.x * 8 + (tid >> 5);
    const int b    = c >> 12;
    const int s    = c & (SS - 1);

    const float cx = g_centers[c * 3 + 0];
    const float cy = g_centers[c * 3 + 1];
    const float cz = g_centers[c * 3 + 2];
    const float ccomp = (lane == 16) ? cx : ((lane == 17) ? cy : cz);
    const int cnt = g_cnt[c];

    float m0 = -3.0e38f, m1 = -3.0e38f, m2 = -3.0e38f, m3 = -3.0e38f;

    auto process4 = [&](const int rows[4], int nv) {
        float fv[4];
#pragma unroll
        for (int e = 0; e < 4; e++) {
            int r = rows[e];
            float v = 0.f;
            if (lane < FIN)          v = x[(size_t)r * FIN + lane];
            else if (lane < FIN + 3) v = pos[(size_t)r * 3 + (lane - FIN)] - ccomp;
            fv[e] = (e < nv) ? v : 0.f;
        }
        float a0[4], a1[4];
#pragma unroll
        for (int e = 0; e < 4; e++) { a0[e] = sb1[lane]; a1[e] = sb1[lane + 32]; }
#pragma unroll
        for (int i = 0; i < FIN + 3; i++) {
            float w0 = sW1[i * 64 + lane];
            float w1 = sW1[i * 64 + 32 + lane];
#pragma unroll
            for (int e = 0; e < 4; e++) {
                float v = __shfl_sync(0xffffffffu, fv[e], i);
                a0[e] = fmaf(v, w0, a0[e]);
                a1[e] = fmaf(v, w1, a1[e]);
            }
        }
#pragma unroll
        for (int e = 0; e < 4; e++) { a0[e] = fmaxf(a0[e], 0.f); a1[e] = fmaxf(a1[e], 0.f); }

        float g0[4], g1[4];
#pragma unroll
        for (int e = 0; e < 4; e++) { g0[e] = sb2[lane]; g1[e] = sb2[lane + 32]; }
#pragma unroll
        for (int i = 0; i < 64; i++) {
            float w0 = sW2[i * 64 + lane];
            float w1 = sW2[i * 64 + 32 + lane];
#pragma unroll
            for (int e = 0; e < 4; e++) {
                float v = (i < 32) ? __shfl_sync(0xffffffffu, a0[e], i)
                                   : __shfl_sync(0xffffffffu, a1[e], i - 32);
                g0[e] = fmaf(v, w0, g0[e]);
                g1[e] = fmaf(v, w1, g1[e]);
            }
        }
#pragma unroll
        for (int e = 0; e < 4; e++) { g0[e] = fmaxf(g0[e], 0.f); g1[e] = fmaxf(g1[e], 0.f); }

        float h0[4], h1v[4], h2v[4], h3v[4];
#pragma unroll
        for (int e = 0; e < 4; e++) {
            h0[e]  = sb3[lane];       h1v[e] = sb3[lane + 32];
            h2v[e] = sb3[lane + 64];  h3v[e] = sb3[lane + 96];
        }
#pragma unroll
        for (int i = 0; i < 64; i++) {
            float w0 = sW3[i * 128 + lane];
            float w1 = sW3[i * 128 + 32 + lane];
            float w2 = sW3[i * 128 + 64 + lane];
            float w3 = sW3[i * 128 + 96 + lane];
#pragma unroll
            for (int e = 0; e < 4; e++) {
                float v = (i < 32) ? __shfl_sync(0xffffffffu, g0[e], i)
                                   : __shfl_sync(0xffffffffu, g1[e], i - 32);
                h0[e]  = fmaf(v, w0, h0[e]);
                h1v[e] = fmaf(v, w1, h1v[e]);
                h2v[e] = fmaf(v, w2, h2v[e]);
                h3v[e] = fmaf(v, w3, h3v[e]);
            }
        }
#pragma unroll
        for (int e = 0; e < 4; e++) {
            if (e < nv) {
                m0 = fmaxf(m0, h0[e]);  m1 = fmaxf(m1, h1v[e]);
                m2 = fmaxf(m2, h2v[e]); m3 = fmaxf(m3, h3v[e]);
            }
        }
    };

    for (int eb = 0; eb < cnt; eb += 4) {
        int nv = min(4, cnt - eb);
        int rows[4];
#pragma unroll
        for (int e = 0; e < 4; e++) {
            int kk = eb + ((e < nv) ? e : 0);
            rows[e] = b * NN + g_nbr[c * KK + kk];
        }
        process4(rows, nv);
    }
    {
        int dflat = b * SS + s;
        int rows[4] = { dflat, dflat, dflat, dflat };
        process4(rows, 1);
    }

    out_x[(size_t)c * HOUT + lane]      = m0;
    out_x[(size_t)c * HOUT + lane + 32] = m1;
    out_x[(size_t)c * HOUT + lane + 64] = m2;
    out_x[(size_t)c * HOUT + lane + 96] = m3;
}

// ===========================================================================
// launch
// ===========================================================================
extern "C" void kernel_launch(void* const* d_in, const int* in_sizes, int n_in,
                              void* d_out, int out_size)
{
    const float* x   = (const float*)d_in[0];
    const float* pos = (const float*)d_in[1];
    const float* W1 = (const float*)d_in[3];
    const float* B1 = (const float*)d_in[4];
    const float* W2 = (const float*)d_in[5];
    const float* B2 = (const float*)d_in[6];
    const float* W3 = (const float*)d_in[7];
    const float* B3 = (const float*)d_in[8];

    float* out_x = (float*)d_out;
    float* out_c = out_x + (size_t)BB * SS * HOUT;
    float* out_b = out_c + (size_t)BB * SS * 3;

    const size_t fps_smem = (size_t)3 * NN * sizeof(float);   // 192 KB dynamic
    const size_t mlp_smem = (size_t)13760 * sizeof(float);
    cudaFuncSetAttribute(fps_kernel, cudaFuncAttributeMaxDynamicSharedMemorySize, (int)fps_smem);
    cudaFuncSetAttribute(mlp_kernel, cudaFuncAttributeMaxDynamicSharedMemorySize, (int)mlp_smem);

    init_hist_kernel<<<(BB * NCELL + 255) / 256, 256>>>();
    cell_count_kernel<<<(BB * NN + 255) / 256, 256>>>(pos);
    cell_scan_kernel<<<BB, NCELL>>>();
    cell_scatter_kernel<<<(BB * NN + 255) / 256, 256>>>(pos);
    fps_kernel<<<BB, 512, fps_smem>>>(pos, out_c);
    ballq_kernel<<<(BB * SS * 32) / 256, 256>>>(pos, out_b);
    mlp_kernel<<<(BB * SS) / 8, 256, mlp_smem>>>(x, pos, W1, B1, W2, B2, W3, B3, out_x);
}

// round 14
// speedup vs baseline: 1.1540x; 1.0145x over previous
#include <cuda_runtime.h>
#include <cstdint>

// ---------------------------------------------------------------------------
// SetAbstraction (PointNet++): FPS -> ball query -> MLP -> max
// B=2, N=16384, S=4096, K=32, F_IN=16, hidden 64-64-128
// Round 14 FPS: R13 (32-point slice pruning, packed REDUX, single barrier)
// widened to 1024 threads / 32 warps x 16 slices each (slice = w + 32*l,
// lanes 0..15 own). Slowest-warp touched count halves -> barrier skew and
// scan term shrink. Everything else identical to R13.
// Selection sequence bit-identical to the naive scan.
// ---------------------------------------------------------------------------

#define BB   2
#define NN   16384
#define SS   4096
#define KK   32
#define FIN  16
#define HOUT 128
#define GC    8
#define NCELL 512
#define FULLM 0xffffffffu

// ---- scratch (__device__ globals; no allocation allowed) -------------------
__device__ float g_centers[BB * SS * 3];
__device__ int   g_nbr[BB * SS * KK];
__device__ int   g_cnt[BB * SS];

__device__ float2 g_sxy[BB * NN];      // sorted (x,y)
__device__ int2   g_szi[BB * NN];      // sorted (z bits, orig idx)
__device__ int    g_hist[BB * NCELL];
__device__ int    g_cstart[BB * (NCELL + 1)];
__device__ int    g_fill[BB * NCELL];

__device__ __forceinline__ int cell_of(float x, float y, float z) {
    int ix = (int)(x * (float)GC); ix = ix < 0 ? 0 : (ix > GC - 1 ? GC - 1 : ix);
    int iy = (int)(y * (float)GC); iy = iy < 0 ? 0 : (iy > GC - 1 ? GC - 1 : iy);
    int iz = (int)(z * (float)GC); iz = iz < 0 ? 0 : (iz > GC - 1 ? GC - 1 : iz);
    return (iz * GC + iy) * GC + ix;
}

// ===========================================================================
// Preprocessing: histogram -> scan -> scatter (counting sort by cell)
// ===========================================================================
__global__ void init_hist_kernel() {
    int i = blockIdx.x * blockDim.x + threadIdx.x;
    if (i < BB * NCELL) g_hist[i] = 0;
}

__global__ void cell_count_kernel(const float* __restrict__ pos) {
    int i = blockIdx.x * blockDim.x + threadIdx.x;
    if (i >= BB * NN) return;
    int b = i >> 14;
    float x = pos[(size_t)i * 3 + 0], y = pos[(size_t)i * 3 + 1], z = pos[(size_t)i * 3 + 2];
    atomicAdd(&g_hist[b * NCELL + cell_of(x, y, z)], 1);
}

__global__ void cell_scan_kernel() {
    __shared__ int sh[NCELL];
    __shared__ int ss[NCELL + 1];
    int b = blockIdx.x, tid = threadIdx.x;
    if (tid < NCELL) sh[tid] = g_hist[b * NCELL + tid];
    __syncthreads();
    if (tid == 0) {
        int acc = 0;
        for (int c = 0; c < NCELL; c++) { ss[c] = acc; acc += sh[c]; }
        ss[NCELL] = acc;
    }
    __syncthreads();
    if (tid < NCELL) {
        g_cstart[b * (NCELL + 1) + tid] = ss[tid];
        g_fill[b * NCELL + tid] = ss[tid];
    }
    if (tid == 0) g_cstart[b * (NCELL + 1) + NCELL] = ss[NCELL];
}

__global__ void cell_scatter_kernel(const float* __restrict__ pos) {
    int i = blockIdx.x * blockDim.x + threadIdx.x;
    if (i >= BB * NN) return;
    int b = i >> 14;
    int li = i & (NN - 1);
    float x = pos[(size_t)i * 3 + 0], y = pos[(size_t)i * 3 + 1], z = pos[(size_t)i * 3 + 2];
    int c = cell_of(x, y, z);
    int p = atomicAdd(&g_fill[b * NCELL + c], 1);
    g_sxy[b * NN + p] = make_float2(x, y);
    g_szi[b * NN + p] = make_int2(__float_as_int(z), li);
}

// ===========================================================================
// Kernel 1: slice-pruned exact FPS. One block per batch, 1024 threads (32 warps).
// Lane l (<16) of warp w owns slice sl = w + 32*l; st = sl*32.
// Per-lane scan key u64 = (dmin_bits<<28)|(~origidx&0x3fff)<<14|sorted_pos.
// ONE __syncthreads per iteration (double-buffered partials).
// ===========================================================================
__global__ void __launch_bounds__(1024, 1)
fps_kernel(const float* __restrict__ pos, float* __restrict__ out_centers)
{
    extern __shared__ float sm[];
    float2* s_xy   = (float2*)sm;        // NN float2 (128 KB)
    float*  s_dmin = sm + 2 * NN;        // NN floats (64 KB)

    __shared__ unsigned long long s_part[2][32];  // parity-buffered partials

    const int b = blockIdx.x, tid = threadIdx.x;
    const int w = tid >> 5, lane = tid & 31;
    const bool owner = lane < 16;
    const int base = b * NN;
    const int2* __restrict__ gz = g_szi + base;

    for (int p = tid; p < NN; p += 1024) {
        s_xy[p] = g_sxy[base + p];
        s_dmin[p] = 1e10f;
    }
    if (tid < 32) { s_part[0][tid] = 0ULL; s_part[1][tid] = 0ULL; }
    __syncthreads();

    // --- one-time per-slice AABB (cooperative: 6 REDUX per slice) ----------
    // lane l (<16) owns slice sl = w + 32*l, st_own = sl*32
    const int st_own = owner ? ((w + (lane << 5)) << 5) : 0;
    float lox = 0.f, hix = 0.f, loy = 0.f, hiy = 0.f, loz = 0.f, hiz = 0.f;
    for (int j = 0; j < 16; j++) {
        int st = (w + (j << 5)) << 5;
        int p = st + lane;
        float2 xy = s_xy[p];
        float  zz = __int_as_float(gz[p].x);
        // coords are in [0,1): nonneg float bits are value-monotonic
        unsigned mnx = __reduce_min_sync(FULLM, __float_as_uint(xy.x));
        unsigned mxx = __reduce_max_sync(FULLM, __float_as_uint(xy.x));
        unsigned mny = __reduce_min_sync(FULLM, __float_as_uint(xy.y));
        unsigned mxy = __reduce_max_sync(FULLM, __float_as_uint(xy.y));
        unsigned mnz = __reduce_min_sync(FULLM, __float_as_uint(zz));
        unsigned mxz = __reduce_max_sync(FULLM, __float_as_uint(zz));
        if (lane == j) {
            lox = __uint_as_float(mnx) - 1e-5f; hix = __uint_as_float(mxx) + 1e-5f;
            loy = __uint_as_float(mny) - 1e-5f; hiy = __uint_as_float(mxy) + 1e-5f;
            loz = __uint_as_float(mnz) - 1e-5f; hiz = __uint_as_float(mxz) + 1e-5f;
        }
    }

    unsigned kv    = owner ? __float_as_uint(1e10f) : 0u;  // slice key cache
    unsigned kcand = 0u;                                   // (lo14<<14)|p

    // initial center (deterministic start at original point 0), in registers
    float cx = pos[(size_t)base * 3 + 0];
    float cy = pos[(size_t)base * 3 + 1];
    float cz = pos[(size_t)base * 3 + 2];
    if (tid == 0) {
        int row = b * SS;
        out_centers[row * 3 + 0] = cx; out_centers[row * 3 + 1] = cy; out_centers[row * 3 + 2] = cz;
        g_centers[row * 3 + 0]   = cx; g_centers[row * 3 + 1]   = cy; g_centers[row * 3 + 2]   = cz;
    }
    __syncthreads();

    for (int t = 1; t < SS; t++) {
        const int par = t & 1;

        // --- prune: each owner lane checks its own slice AABB ---------------
        float pdx = fmaxf(fmaxf(lox - cx, cx - hix), 0.f);
        float pdy = fmaxf(fmaxf(loy - cy, cy - hiy), 0.f);
        float pdz = fmaxf(fmaxf(loz - cz, cz - hiz), 0.f);
        float lb  = (pdx * pdx + pdy * pdy + pdz * pdz) * 0.999f;
        bool touched = lb < __uint_as_float(kv);   // non-owners: lb>=0==kv -> false

        // self-prefetch own slice's two z/idx lines (fire-and-forget)
        if (touched) {
            const int2* pf0 = &gz[st_own];
            asm volatile("prefetch.global.L1 [%0];" :: "l"(pf0));
            const int2* pf1 = &gz[st_own + 16];
            asm volatile("prefetch.global.L1 [%0];" :: "l"(pf1));
        }
        unsigned tmask = __ballot_sync(FULLM, touched);

        if (tmask) {
            // --- process touched slices (1 chunk each, pipelined preload) --
            int j = __ffs(tmask) - 1; tmask &= tmask - 1;
            int p = ((w + (j << 5)) << 5) + lane;
            int2 zi = gz[p];
            float2 xy = s_xy[p];
            while (j >= 0) {
                float zz  = __int_as_float(zi.x);
                float ddx = __fsub_rn(xy.x, cx);
                float ddy = __fsub_rn(xy.y, cy);
                float ddz = __fsub_rn(zz,   cz);
                float d   = __fadd_rn(__fadd_rn(__fmul_rn(ddx, ddx), __fmul_rn(ddy, ddy)),
                                      __fmul_rn(ddz, ddz));
                float dm  = fminf(s_dmin[p], d);
                s_dmin[p] = dm;
                unsigned lo14 = (~(unsigned)zi.y) & 0x3fffu;
                unsigned long long best =
                    (((unsigned long long)__float_as_uint(dm)) << 28)
                    | ((unsigned long long)lo14 << 14)
                    | (unsigned long long)p;

                // preload next touched slice
                int jn = -1, pn = 0;
                int2 zin = make_int2(0, 0); float2 xyn = make_float2(0.f, 0.f);
                if (tmask) {
                    jn = __ffs(tmask) - 1; tmask &= tmask - 1;
                    pn = ((w + (jn << 5)) << 5) + lane;
                    zin = gz[pn]; xyn = s_xy[pn];
                }

                // slice key via packed REDUX (identity rides in the value)
                unsigned du    = (unsigned)(best >> 28);
                unsigned wm    = __reduce_max_sync(FULLM, du);
                unsigned cand  = (du == wm) ? (unsigned)(best & 0xFFFFFFFull) : 0u;
                unsigned mcand = __reduce_max_sync(FULLM, cand);
                if (lane == j) { kv = wm; kcand = mcand; }
                j = jn; p = pn; zi = zin; xy = xyn;
            }

            // per-warp partial over its 16 owned slices -> parity buffer
            unsigned mv  = __reduce_max_sync(FULLM, kv);
            unsigned c2  = (kv == mv) ? kcand : 0u;
            unsigned mc2 = __reduce_max_sync(FULLM, c2);
            if (kv == mv && kcand == mc2) {   // unique (mc2 embeds unique p)
                s_part[par][w] = (((unsigned long long)mv) << 32) | mc2;
            }
        } else {
            // untouched warp: partial unchanged; copy across parity
            if (lane == 0) s_part[par][w] = s_part[par ^ 1][w];
        }
        __syncthreads();   // the ONLY barrier per iteration

        // --- redundant final argmax over 32 partials (every warp) ----------
        unsigned long long pk = s_part[par][lane];
        unsigned hi = (unsigned)(pk >> 32), lo = (unsigned)pk;
        unsigned mv2 = __reduce_max_sync(FULLM, hi);
        unsigned c3  = (hi == mv2) ? lo : 0u;
        unsigned mc3 = __reduce_max_sync(FULLM, c3);
        int wp  = (int)(mc3 & 0x3fffu);
        float2 xyw = s_xy[wp];                       // broadcast LDS
        float  zw  = __int_as_float(gz[wp].x);       // uniform LDG, L1-hot
        cx = xyw.x; cy = xyw.y; cz = zw;             // next center, in regs
        if (w == 0 && hi == mv2 && lo == mc3) {      // unique winner lane
            int row = b * SS + t;
            out_centers[row * 3 + 0] = cx; out_centers[row * 3 + 1] = cy; out_centers[row * 3 + 2] = cz;
            g_centers[row * 3 + 0]   = cx; g_centers[row * 3 + 1]   = cy; g_centers[row * 3 + 2]   = cz;
        }
    }
}

// ===========================================================================
// Kernel 2: Ball query — one warp per center; ordered scan, first K within R.
// ===========================================================================
__global__ void __launch_bounds__(256, 8)
ballq_kernel(const float* __restrict__ pos, float* __restrict__ out_batch)
{
    const int w    = (blockIdx.x * blockDim.x + threadIdx.x) >> 5;
    const int lane = threadIdx.x & 31;
    if (w >= BB * SS) return;

    const int b = w >> 12;
    const int s = w & (SS - 1);
    const float* pb = pos + (size_t)b * NN * 3;

    const float cx = g_centers[w * 3 + 0];
    const float cy = g_centers[w * 3 + 1];
    const float cz = g_centers[w * 3 + 2];
    const float R2 = (float)(0.1 * 0.1);
    const int excl = s - b * (NN - SS);

    int cnt = 0;
    for (int j0 = 0; j0 < NN && cnt < KK; j0 += 32) {
        int j = j0 + lane;
        float x_ = pb[j * 3 + 0];
        float y_ = pb[j * 3 + 1];
        float z_ = pb[j * 3 + 2];
        float dx = __fsub_rn(cx, x_);
        float dy = __fsub_rn(cy, y_);
        float dz = __fsub_rn(cz, z_);
        float d2 = __fadd_rn(__fadd_rn(__fmul_rn(dx, dx), __fmul_rn(dy, dy)),
                             __fmul_rn(dz, dz));
        bool hit = (d2 <= R2) && (j != excl);
        unsigned m = __ballot_sync(0xffffffffu, hit);
        while (m && cnt < KK) {
            int bit = __ffs(m) - 1;
            if (lane == bit) g_nbr[w * KK + cnt] = j0 + bit;
            cnt++;
            m &= m - 1;
        }
    }
    if (lane == 0) {
        g_cnt[w] = cnt;
        out_batch[w] = (float)b;
    }
}

// ===========================================================================
// Kernel 3: gather + MLP(19->64->64->128) + max over K+1 (unchanged).
// ===========================================================================
__global__ void __launch_bounds__(256, 1)
mlp_kernel(const float* __restrict__ x, const float* __restrict__ pos,
           const float* __restrict__ W1, const float* __restrict__ B1,
           const float* __restrict__ W2, const float* __restrict__ B2,
           const float* __restrict__ W3, const float* __restrict__ B3,
           float* __restrict__ out_x)
{
    extern __shared__ float sw[];
    float* sW1 = sw;
    float* sb1 = sW1 + 19 * 64;
    float* sW2 = sb1 + 64;
    float* sb2 = sW2 + 4096;
    float* sW3 = sb2 + 64;
    float* sb3 = sW3 + 8192;

    const int tid = threadIdx.x;
    for (int i = tid; i < 19 * 64; i += 256) sW1[i] = W1[i];
    for (int i = tid; i < 64;      i += 256) sb1[i] = B1[i];
    for (int i = tid; i < 64 * 64; i += 256) sW2[i] = W2[i];
    for (int i = tid; i < 64;      i += 256) sb2[i] = B2[i];
    for (int i = tid; i < 64 * 128; i += 256) sW3[i] = W3[i];
    for (int i = tid; i < 128;     i += 256) sb3[i] = B3[i];
    __syncthreads();

    const int lane = tid & 31;
    const int c    = blockIdx.x * 8 + (tid >> 5);
    const int b    = c >> 12;
    const int s    = c & (SS - 1);

    const float cx = g_centers[c * 3 + 0];
    const float cy = g_centers[c * 3 + 1];
    const float cz = g_centers[c * 3 + 2];
    const float ccomp = (lane == 16) ? cx : ((lane == 17) ? cy : cz);
    const int cnt = g_cnt[c];

    float m0 = -3.0e38f, m1 = -3.0e38f, m2 = -3.0e38f, m3 = -3.0e38f;

    auto process4 = [&](const int rows[4], int nv) {
        float fv[4];
#pragma unroll
        for (int e = 0; e < 4; e++) {
            int r = rows[e];
            float v = 0.f;
            if (lane < FIN)          v = x[(size_t)r * FIN + lane];
            else if (lane < FIN + 3) v = pos[(size_t)r * 3 + (lane - FIN)] - ccomp;
            fv[e] = (e < nv) ? v : 0.f;
        }
        float a0[4], a1[4];
#pragma unroll
        for (int e = 0; e < 4; e++) { a0[e] = sb1[lane]; a1[e] = sb1[lane + 32]; }
#pragma unroll
        for (int i = 0; i < FIN + 3; i++) {
            float w0 = sW1[i * 64 + lane];
            float w1 = sW1[i * 64 + 32 + lane];
#pragma unroll
            for (int e = 0; e < 4; e++) {
                float v = __shfl_sync(0xffffffffu, fv[e], i);
                a0[e] = fmaf(v, w0, a0[e]);
                a1[e] = fmaf(v, w1, a1[e]);
            }
        }
#pragma unroll
        for (int e = 0; e < 4; e++) { a0[e] = fmaxf(a0[e], 0.f); a1[e] = fmaxf(a1[e], 0.f); }

        float g0[4], g1[4];
#pragma unroll
        for (int e = 0; e < 4; e++) { g0[e] = sb2[lane]; g1[e] = sb2[lane + 32]; }
#pragma unroll
        for (int i = 0; i < 64; i++) {
            float w0 = sW2[i * 64 + lane];
            float w1 = sW2[i * 64 + 32 + lane];
#pragma unroll
            for (int e = 0; e < 4; e++) {
                float v = (i < 32) ? __shfl_sync(0xffffffffu, a0[e], i)
                                   : __shfl_sync(0xffffffffu, a1[e], i - 32);
                g0[e] = fmaf(v, w0, g0[e]);
                g1[e] = fmaf(v, w1, g1[e]);
            }
        }
#pragma unroll
        for (int e = 0; e < 4; e++) { g0[e] = fmaxf(g0[e], 0.f); g1[e] = fmaxf(g1[e], 0.f); }

        float h0[4], h1v[4], h2v[4], h3v[4];
#pragma unroll
        for (int e = 0; e < 4; e++) {
            h0[e]  = sb3[lane];       h1v[e] = sb3[lane + 32];
            h2v[e] = sb3[lane + 64];  h3v[e] = sb3[lane + 96];
        }
#pragma unroll
        for (int i = 0; i < 64; i++) {
            float w0 = sW3[i * 128 + lane];
            float w1 = sW3[i * 128 + 32 + lane];
            float w2 = sW3[i * 128 + 64 + lane];
            float w3 = sW3[i * 128 + 96 + lane];
#pragma unroll
            for (int e = 0; e < 4; e++) {
                float v = (i < 32) ? __shfl_sync(0xffffffffu, g0[e], i)
                                   : __shfl_sync(0xffffffffu, g1[e], i - 32);
                h0[e]  = fmaf(v, w0, h0[e]);
                h1v[e] = fmaf(v, w1, h1v[e]);
                h2v[e] = fmaf(v, w2, h2v[e]);
                h3v[e] = fmaf(v, w3, h3v[e]);
            }
        }
#pragma unroll
        for (int e = 0; e < 4; e++) {
            if (e < nv) {
                m0 = fmaxf(m0, h0[e]);  m1 = fmaxf(m1, h1v[e]);
                m2 = fmaxf(m2, h2v[e]); m3 = fmaxf(m3, h3v[e]);
            }
        }
    };

    for (int eb = 0; eb < cnt; eb += 4) {
        int nv = min(4, cnt - eb);
        int rows[4];
#pragma unroll
        for (int e = 0; e < 4; e++) {
            int kk = eb + ((e < nv) ? e : 0);
            rows[e] = b * NN + g_nbr[c * KK + kk];
        }
        process4(rows, nv);
    }
    {
        int dflat = b * SS + s;
        int rows[4] = { dflat, dflat, dflat, dflat };
        process4(rows, 1);
    }

    out_x[(size_t)c * HOUT + lane]      = m0;
    out_x[(size_t)c * HOUT + lane + 32] = m1;
    out_x[(size_t)c * HOUT + lane + 64] = m2;
    out_x[(size_t)c * HOUT + lane + 96] = m3;
}

// ===========================================================================
// launch
// ===========================================================================
extern "C" void kernel_launch(void* const* d_in, const int* in_sizes, int n_in,
                              void* d_out, int out_size)
{
    const float* x   = (const float*)d_in[0];
    const float* pos = (const float*)d_in[1];
    const float* W1 = (const float*)d_in[3];
    const float* B1 = (const float*)d_in[4];
    const float* W2 = (const float*)d_in[5];
    const float* B2 = (const float*)d_in[6];
    const float* W3 = (const float*)d_in[7];
    const float* B3 = (const float*)d_in[8];

    float* out_x = (float*)d_out;
    float* out_c = out_x + (size_t)BB * SS * HOUT;
    float* out_b = out_c + (size_t)BB * SS * 3;

    const size_t fps_smem = (size_t)3 * NN * sizeof(float);   // 192 KB dynamic
    const size_t mlp_smem = (size_t)13760 * sizeof(float);
    cudaFuncSetAttribute(fps_kernel, cudaFuncAttributeMaxDynamicSharedMemorySize, (int)fps_smem);
    cudaFuncSetAttribute(mlp_kernel, cudaFuncAttributeMaxDynamicSharedMemorySize, (int)mlp_smem);

    init_hist_kernel<<<(BB * NCELL + 255) / 256, 256>>>();
    cell_count_kernel<<<(BB * NN + 255) / 256, 256>>>(pos);
    cell_scan_kernel<<<BB, NCELL>>>();
    cell_scatter_kernel<<<(BB * NN + 255) / 256, 256>>>(pos);
    fps_kernel<<<BB, 1024, fps_smem>>>(pos, out_c);
    ballq_kernel<<<(BB * SS * 32) / 256, 256>>>(pos, out_b);
    mlp_kernel<<<(BB * SS) / 8, 256, mlp_smem>>>(x, pos, W1, B1, W2, B2, W3, B3, out_x);
}